// round 3
// baseline (speedup 1.0000x reference)
#include <cuda_runtime.h>

#define BATCH 64
#define N     4096
#define NX    128
#define NU    32
#define NY    32
#define L     64           // chunk length
#define NCHUNK (N / L)     // 64

#define Y_ELEMS ((size_t)BATCH * N * NY)

// Scratch (no cudaMalloc allowed)
__device__ float g_P0[NX * NX];
__device__ float g_P1[NX * NX];
__device__ float g_XS[BATCH * NCHUNK * NX]; // chunk start states x_{cL}

// ---------------------------------------------------------------------------
// 128x128 matrix square: out = in * in. grid=128 (row), block=128 (col).
// ---------------------------------------------------------------------------
__global__ void __launch_bounds__(NX) matsq(const float* __restrict__ in,
                                            float* __restrict__ out)
{
    __shared__ float row[NX];
    const int r = blockIdx.x, c = threadIdx.x;
    row[c] = in[r * NX + c];
    __syncthreads();
    float acc = 0.f;
#pragma unroll 16
    for (int j = 0; j < NX; j++) acc += row[j] * in[j * NX + c];
    out[r * NX + c] = acc;
}

// ---------------------------------------------------------------------------
// Pass 1: local scans, TWO batches per CTA (b and b+32) sharing A/B registers.
// grid=(NCHUNK, BATCH/2), block=128. Writes local contributions w_k into
// xout for k=1..L for both streams.
// ---------------------------------------------------------------------------
__global__ void __launch_bounds__(NX, 2) pass1_local(
    const float* __restrict__ d,
    const float* __restrict__ A,
    const float* __restrict__ B,
    float* __restrict__ xout)
{
    __shared__ float xs[2][2][NX];
    __shared__ float us[2][2][NU];

    const int c  = blockIdx.x;
    const int b0 = blockIdx.y;
    const int b1 = blockIdx.y + BATCH / 2;
    const int i  = threadIdx.x;

    float a[NX], bb[NU];
#pragma unroll
    for (int j = 0; j < NX; j++) a[j] = A[i * NX + j];
#pragma unroll
    for (int j = 0; j < NU; j++) bb[j] = B[i * NU + j];

    const float* u0 = d + (size_t)b0 * N * NU + (size_t)c * L * NU;
    const float* u1 = d + (size_t)b1 * N * NU + (size_t)c * L * NU;
    float* xb0 = xout + (size_t)b0 * (N + 1) * NX + (size_t)c * L * NX;
    float* xb1 = xout + (size_t)b1 * (N + 1) * NX + (size_t)c * L * NX;

    if (c == 0) {           // x_0 = 0 for both batches
        xb0[i] = 0.0f;
        xb1[i] = 0.0f;
    }

    xs[0][0][i] = 0.0f;
    xs[0][1][i] = 0.0f;
    if (i < NU) { us[0][0][i] = u0[i]; us[0][1][i] = u1[i]; }
    __syncthreads();

    int p = 0;
    for (int k = 0; k < L; k++) {
        const float4* x40 = (const float4*)xs[p][0];
        const float4* x41 = (const float4*)xs[p][1];
        const float4* u40 = (const float4*)us[p][0];
        const float4* u41 = (const float4*)us[p][1];
        float s00 = 0.f, s01 = 0.f, s02 = 0.f, s03 = 0.f;
        float s10 = 0.f, s11 = 0.f, s12 = 0.f, s13 = 0.f;
#pragma unroll
        for (int j = 0; j < NX / 4; j++) {
            float4 v0 = x40[j];
            float4 v1 = x41[j];
            s00 += a[4 * j + 0] * v0.x;  s10 += a[4 * j + 0] * v1.x;
            s01 += a[4 * j + 1] * v0.y;  s11 += a[4 * j + 1] * v1.y;
            s02 += a[4 * j + 2] * v0.z;  s12 += a[4 * j + 2] * v1.z;
            s03 += a[4 * j + 3] * v0.w;  s13 += a[4 * j + 3] * v1.w;
        }
#pragma unroll
        for (int j = 0; j < NU / 4; j++) {
            float4 v0 = u40[j];
            float4 v1 = u41[j];
            s00 += bb[4 * j + 0] * v0.x; s10 += bb[4 * j + 0] * v1.x;
            s01 += bb[4 * j + 1] * v0.y; s11 += bb[4 * j + 1] * v1.y;
            s02 += bb[4 * j + 2] * v0.z; s12 += bb[4 * j + 2] * v1.z;
            s03 += bb[4 * j + 3] * v0.w; s13 += bb[4 * j + 3] * v1.w;
        }
        float w0 = (s00 + s01) + (s02 + s03);
        float w1 = (s10 + s11) + (s12 + s13);

        xs[p ^ 1][0][i] = w0;
        xs[p ^ 1][1][i] = w1;
        if (i < NU && (k + 1) < L) {
            us[p ^ 1][0][i] = u0[(size_t)(k + 1) * NU + i];
            us[p ^ 1][1][i] = u1[(size_t)(k + 1) * NU + i];
        }
        xb0[(size_t)(k + 1) * NX + i] = w0;
        xb1[(size_t)(k + 1) * NX + i] = w1;
        __syncthreads();
        p ^= 1;
    }
}

// ---------------------------------------------------------------------------
// Pass 2: serial combine across chunks. grid=BATCH, block=128.
// ---------------------------------------------------------------------------
__global__ void __launch_bounds__(NX) pass2_combine(
    const float* __restrict__ A64,
    const float* __restrict__ xout,
    float* __restrict__ XS)
{
    __shared__ float s[NX];
    const int b = blockIdx.x, i = threadIdx.x;

    float a[NX];
#pragma unroll
    for (int j = 0; j < NX; j++) a[j] = A64[i * NX + j];

    const float* xb  = xout + (size_t)b * (N + 1) * NX;
    float*       xsb = XS + (size_t)b * NCHUNK * NX;

    s[i] = 0.f;
    xsb[i] = 0.f;
    __syncthreads();

    for (int c = 0; c < NCHUNK - 1; c++) {
        const float4* s4 = (const float4*)s;
        float acc0 = 0.f, acc1 = 0.f, acc2 = 0.f, acc3 = 0.f;
#pragma unroll
        for (int j = 0; j < NX / 4; j++) {
            float4 v = s4[j];
            acc0 += a[4 * j + 0] * v.x;
            acc1 += a[4 * j + 1] * v.y;
            acc2 += a[4 * j + 2] * v.z;
            acc3 += a[4 * j + 3] * v.w;
        }
        float wl = xb[(size_t)(c + 1) * L * NX + i];
        float ns = (acc0 + acc1) + (acc2 + acc3) + wl;
        __syncthreads();
        s[i] = ns;
        xsb[(size_t)(c + 1) * NX + i] = ns;
        __syncthreads();
    }
}

// ---------------------------------------------------------------------------
// Pass 3: parallel correction, TWO batches per CTA.
// grid=(NCHUNK-1, BATCH/2) with c = blockIdx.x+1.
// ---------------------------------------------------------------------------
__global__ void __launch_bounds__(NX, 2) pass3_fix(
    const float* __restrict__ A,
    const float* __restrict__ XS,
    float* __restrict__ xout)
{
    __shared__ float ps[2][2][NX];
    const int c  = blockIdx.x + 1;
    const int b0 = blockIdx.y;
    const int b1 = blockIdx.y + BATCH / 2;
    const int i  = threadIdx.x;

    float a[NX];
#pragma unroll
    for (int j = 0; j < NX; j++) a[j] = A[i * NX + j];

    float* xb0 = xout + (size_t)b0 * (N + 1) * NX + (size_t)c * L * NX;
    float* xb1 = xout + (size_t)b1 * (N + 1) * NX + (size_t)c * L * NX;

    ps[0][0][i] = XS[((size_t)b0 * NCHUNK + c) * NX + i];
    ps[0][1][i] = XS[((size_t)b1 * NCHUNK + c) * NX + i];
    __syncthreads();

    float nxt0 = xb0[(size_t)1 * NX + i];
    float nxt1 = xb1[(size_t)1 * NX + i];
    int p = 0;
    for (int k = 1; k <= L; k++) {
        const float4* p40 = (const float4*)ps[p][0];
        const float4* p41 = (const float4*)ps[p][1];
        float s00 = 0.f, s01 = 0.f, s02 = 0.f, s03 = 0.f;
        float s10 = 0.f, s11 = 0.f, s12 = 0.f, s13 = 0.f;
#pragma unroll
        for (int j = 0; j < NX / 4; j++) {
            float4 v0 = p40[j];
            float4 v1 = p41[j];
            s00 += a[4 * j + 0] * v0.x;  s10 += a[4 * j + 0] * v1.x;
            s01 += a[4 * j + 1] * v0.y;  s11 += a[4 * j + 1] * v1.y;
            s02 += a[4 * j + 2] * v0.z;  s12 += a[4 * j + 2] * v1.z;
            s03 += a[4 * j + 3] * v0.w;  s13 += a[4 * j + 3] * v1.w;
        }
        float pn0 = (s00 + s01) + (s02 + s03);
        float pn1 = (s10 + s11) + (s12 + s13);

        float cur0 = nxt0, cur1 = nxt1;
        if (k < L) {
            nxt0 = xb0[(size_t)(k + 1) * NX + i];
            nxt1 = xb1[(size_t)(k + 1) * NX + i];
        }
        xb0[(size_t)k * NX + i] = cur0 + pn0;
        xb1[(size_t)k * NX + i] = cur1 + pn1;

        ps[p ^ 1][0][i] = pn0;
        ps[p ^ 1][1][i] = pn1;
        __syncthreads();
        p ^= 1;
    }
}

// ---------------------------------------------------------------------------
// Output kernel: y[b,k,:] = C x[b,k] + D u[b,k] (unchanged).
// ---------------------------------------------------------------------------
#define TCHUNK 64

__global__ void __launch_bounds__(256) y_kernel(
    const float* __restrict__ d,
    const float* __restrict__ C,
    const float* __restrict__ D,
    const float* __restrict__ x,
    float* __restrict__ y)
{
    __shared__ float xsh[TCHUNK][NX];
    __shared__ float ush[TCHUNK][NU];

    const int chunk = blockIdx.x;
    const int b     = blockIdx.y;
    const int tid   = threadIdx.x;

    {
        const float4* xg4 = (const float4*)(x + (size_t)b * (N + 1) * NX
                                              + (size_t)chunk * TCHUNK * NX);
        float4* xs4 = (float4*)&xsh[0][0];
#pragma unroll
        for (int r = 0; r < (TCHUNK * NX / 4) / 256; r++)
            xs4[tid + 256 * r] = xg4[tid + 256 * r];
    }
    {
        const float4* ug4 = (const float4*)(d + (size_t)b * N * NU
                                              + (size_t)chunk * TCHUNK * NU);
        float4* us4 = (float4*)&ush[0][0];
#pragma unroll
        for (int r = 0; r < (TCHUNK * NU / 4) / 256; r++)
            us4[tid + 256 * r] = ug4[tid + 256 * r];
    }
    __syncthreads();

    const int o = tid & 31;
    const int w = tid >> 5;

    float c[NX], dd[NU];
    {
        const float4* c4 = (const float4*)(C + (size_t)o * NX);
#pragma unroll
        for (int j = 0; j < NX / 4; j++) {
            float4 v = c4[j];
            c[4 * j + 0] = v.x; c[4 * j + 1] = v.y;
            c[4 * j + 2] = v.z; c[4 * j + 3] = v.w;
        }
        const float4* d4 = (const float4*)(D + (size_t)o * NU);
#pragma unroll
        for (int j = 0; j < NU / 4; j++) {
            float4 v = d4[j];
            dd[4 * j + 0] = v.x; dd[4 * j + 1] = v.y;
            dd[4 * j + 2] = v.z; dd[4 * j + 3] = v.w;
        }
    }

    float* yb = y + (size_t)b * N * NY + (size_t)chunk * TCHUNK * NY;

#pragma unroll
    for (int tt = 0; tt < 8; tt++) {
        const int t = w * 8 + tt;
        const float4* xr = (const float4*)xsh[t];
        const float4* ur = (const float4*)ush[t];
        float a0 = 0.f, a1 = 0.f, a2 = 0.f, a3 = 0.f;
#pragma unroll
        for (int j = 0; j < NX / 4; j++) {
            float4 v = xr[j];
            a0 += c[4 * j + 0] * v.x;
            a1 += c[4 * j + 1] * v.y;
            a2 += c[4 * j + 2] * v.z;
            a3 += c[4 * j + 3] * v.w;
        }
#pragma unroll
        for (int j = 0; j < NU / 4; j++) {
            float4 v = ur[j];
            a0 += dd[4 * j + 0] * v.x;
            a1 += dd[4 * j + 1] * v.y;
            a2 += dd[4 * j + 2] * v.z;
            a3 += dd[4 * j + 3] * v.w;
        }
        yb[(size_t)t * NY + o] = (a0 + a1) + (a2 + a3);
    }
}

// ---------------------------------------------------------------------------
extern "C" void kernel_launch(void* const* d_in, const int* in_sizes, int n_in,
                              void* d_out, int out_size)
{
    const float* d = (const float*)d_in[0];
    const float* A = (const float*)d_in[1];
    const float* B = (const float*)d_in[2];
    const float* C = (const float*)d_in[3];
    const float* D = (const float*)d_in[4];

    float* y = (float*)d_out;
    float* x = (float*)d_out + Y_ELEMS;

    float* P0;  cudaGetSymbolAddress((void**)&P0, g_P0);
    float* P1;  cudaGetSymbolAddress((void**)&P1, g_P1);
    float* XS;  cudaGetSymbolAddress((void**)&XS, g_XS);

    // Launches #1-#5: A^2 .. A^32 (pass1 doesn't need them yet)
    matsq<<<NX, NX>>>(A,  P0);   // A^2
    matsq<<<NX, NX>>>(P0, P1);   // A^4
    matsq<<<NX, NX>>>(P1, P0);   // A^8
    matsq<<<NX, NX>>>(P0, P1);   // A^16
    matsq<<<NX, NX>>>(P1, P0);   // A^32

    // Launch #6 (ncu -s 5 -c 1 profiles this one): pass1
    {
        dim3 g(NCHUNK, BATCH / 2);
        pass1_local<<<g, NX>>>(d, A, B, x);
    }

    // Launch #7: A^64
    matsq<<<NX, NX>>>(P0, P1);   // A^64 (in P1)

    // Pass 2: serial chunk combine
    pass2_combine<<<BATCH, NX>>>(P1, x, XS);

    // Pass 3: parallel correction
    {
        dim3 g(NCHUNK - 1, BATCH / 2);
        pass3_fix<<<g, NX>>>(A, XS, x);
    }

    // Output projection
    {
        dim3 g(N / TCHUNK, BATCH);
        y_kernel<<<g, 256>>>(d, C, D, x, y);
    }
}